// round 1
// baseline (speedup 1.0000x reference)
#include <cuda_runtime.h>
#include <cfloat>

#define B_  8
#define C_  512
#define L_  2048
#define CQ_ 64
#define KW  3
#define CK  (C_ * KW)   // 1536
#define COUT (CQ_ + CQ_ + C_)  // 640

// Scratch (allocation-free rule: __device__ globals)
__device__ float g_q[B_ * CQ_ * L_];            // 4 MB
__device__ float g_k[B_ * CQ_ * L_];            // 4 MB
__device__ float g_v[B_ * C_ * L_];             // 32 MB
__device__ float g_sT[(size_t)B_ * L_ * L_];    // 128 MB  (scores^T, softmaxed in place)

// ---------------------------------------------------------------------------
// Kernel 1: fused QKV conv as implicit GEMM.
//   y[b, o, l] = sum_{ci,kk} W[o, ci, kk] * x[b, ci, l + kk - 1]   (zero pad)
// o in [0,64) -> q, [64,128) -> k, [128,640) -> v.
// Tile: 128(o) x 128(l), K-chunk 8 over flattened (ci,kk) of size 1536.
// ---------------------------------------------------------------------------
__device__ __forceinline__ const float* wrow(const float* __restrict__ Wq,
                                             const float* __restrict__ Wk,
                                             const float* __restrict__ Wv,
                                             int o) {
    if (o < CQ_)        return Wq + (size_t)o * CK;
    if (o < 2 * CQ_)    return Wk + (size_t)(o - CQ_) * CK;
    return Wv + (size_t)(o - 2 * CQ_) * CK;
}

__global__ __launch_bounds__(256, 2)
void conv_qkv_kernel(const float* __restrict__ x,
                     const float* __restrict__ Wq,
                     const float* __restrict__ Wk,
                     const float* __restrict__ Wv) {
    __shared__ float As[8][128];   // [kchunk][o]
    __shared__ float Bs[8][128];   // [kchunk][l]

    const int b  = blockIdx.z;
    const int o0 = blockIdx.y * 128;
    const int l0 = blockIdx.x * 128;
    const int t  = threadIdx.x;

    const int m0 = (t >> 4) * 8;   // o micro offset
    const int n0 = (t & 15) * 8;   // l micro offset

    // A-load mapping: thread t loads 4 consecutive k-indices for one o row
    const int a_oo = t >> 1;
    const int a_r4 = (t & 1) * 4;
    const float* wr = wrow(Wq, Wk, Wv, o0 + a_oo);

    float acc[8][8];
#pragma unroll
    for (int i = 0; i < 8; ++i)
#pragma unroll
        for (int j = 0; j < 8; ++j) acc[i][j] = 0.f;

    for (int kb = 0; kb < CK; kb += 8) {
        // load weights (transposed into smem)
        float4 wv4 = *reinterpret_cast<const float4*>(wr + kb + a_r4);
        As[a_r4 + 0][a_oo] = wv4.x;
        As[a_r4 + 1][a_oo] = wv4.y;
        As[a_r4 + 2][a_oo] = wv4.z;
        As[a_r4 + 3][a_oo] = wv4.w;

        // load im2col(x)
#pragma unroll
        for (int i = t; i < 8 * 128; i += 256) {
            int r  = i >> 7;
            int ll = i & 127;
            int kidx = kb + r;
            int ci = kidx / 3;
            int kk = kidx - ci * 3;
            int lpos = l0 + ll + kk - 1;
            float xv = 0.f;
            if (lpos >= 0 && lpos < L_)
                xv = x[((size_t)b * C_ + ci) * L_ + lpos];
            Bs[r][ll] = xv;
        }
        __syncthreads();

#pragma unroll
        for (int r = 0; r < 8; ++r) {
            float4 a0 = *reinterpret_cast<const float4*>(&As[r][m0]);
            float4 a1 = *reinterpret_cast<const float4*>(&As[r][m0 + 4]);
            float4 b0 = *reinterpret_cast<const float4*>(&Bs[r][n0]);
            float4 b1 = *reinterpret_cast<const float4*>(&Bs[r][n0 + 4]);
            float av[8] = {a0.x, a0.y, a0.z, a0.w, a1.x, a1.y, a1.z, a1.w};
            float bv[8] = {b0.x, b0.y, b0.z, b0.w, b1.x, b1.y, b1.z, b1.w};
#pragma unroll
            for (int mi = 0; mi < 8; ++mi)
#pragma unroll
                for (int ni = 0; ni < 8; ++ni)
                    acc[mi][ni] += av[mi] * bv[ni];
        }
        __syncthreads();
    }

    // store with q/k/v routing
#pragma unroll
    for (int mi = 0; mi < 8; ++mi) {
        int o = o0 + m0 + mi;
        float* dst;
        if (o < CQ_)            dst = &g_q[((size_t)b * CQ_ + o) * L_];
        else if (o < 2 * CQ_)   dst = &g_k[((size_t)b * CQ_ + (o - CQ_)) * L_];
        else                    dst = &g_v[((size_t)b * C_ + (o - 2 * CQ_)) * L_];
#pragma unroll
        for (int ni = 0; ni < 8; ++ni)
            dst[l0 + n0 + ni] = acc[mi][ni];
    }
}

// ---------------------------------------------------------------------------
// Kernel 2: scores^T.  sT[b, j, i] = sum_c k[b,c,j] * q[b,c,i].  K = 64.
// Both operands are c-major with contiguous j/i -> direct coalesced smem loads.
// ---------------------------------------------------------------------------
__global__ __launch_bounds__(256, 2)
void scores_kernel() {
    __shared__ float As[8][128];   // [c][j]
    __shared__ float Bs[8][128];   // [c][i]

    const int b  = blockIdx.z;
    const int j0 = blockIdx.y * 128;
    const int i0 = blockIdx.x * 128;
    const int t  = threadIdx.x;
    const int m0 = (t >> 4) * 8;
    const int n0 = (t & 15) * 8;

    float acc[8][8];
#pragma unroll
    for (int i = 0; i < 8; ++i)
#pragma unroll
        for (int j = 0; j < 8; ++j) acc[i][j] = 0.f;

    for (int kb = 0; kb < CQ_; kb += 8) {
#pragma unroll
        for (int i = t; i < 8 * 128; i += 256) {
            int r  = i >> 7;
            int cc = i & 127;
            size_t rowb = ((size_t)b * CQ_ + kb + r) * L_;
            As[r][cc] = g_k[rowb + j0 + cc];
            Bs[r][cc] = g_q[rowb + i0 + cc];
        }
        __syncthreads();

#pragma unroll
        for (int r = 0; r < 8; ++r) {
            float4 a0 = *reinterpret_cast<const float4*>(&As[r][m0]);
            float4 a1 = *reinterpret_cast<const float4*>(&As[r][m0 + 4]);
            float4 b0 = *reinterpret_cast<const float4*>(&Bs[r][n0]);
            float4 b1 = *reinterpret_cast<const float4*>(&Bs[r][n0 + 4]);
            float av[8] = {a0.x, a0.y, a0.z, a0.w, a1.x, a1.y, a1.z, a1.w};
            float bv[8] = {b0.x, b0.y, b0.z, b0.w, b1.x, b1.y, b1.z, b1.w};
#pragma unroll
            for (int mi = 0; mi < 8; ++mi)
#pragma unroll
                for (int ni = 0; ni < 8; ++ni)
                    acc[mi][ni] += av[mi] * bv[ni];
        }
        __syncthreads();
    }

#pragma unroll
    for (int mi = 0; mi < 8; ++mi) {
        size_t rowb = ((size_t)b * L_ + j0 + m0 + mi) * L_;
#pragma unroll
        for (int ni = 0; ni < 8; ++ni)
            g_sT[rowb + i0 + n0 + ni] = acc[mi][ni];
    }
}

// ---------------------------------------------------------------------------
// Kernel 3: in-place row softmax over sT rows (length L). One block per row.
// ---------------------------------------------------------------------------
__global__ __launch_bounds__(256)
void softmax_kernel() {
    __shared__ float red[256];
    const int row = blockIdx.x;          // b*L + j
    const int t   = threadIdx.x;
    size_t base = (size_t)row * L_;

    float v[8];
    float m = -FLT_MAX;
#pragma unroll
    for (int i = 0; i < 8; ++i) {
        v[i] = g_sT[base + t + i * 256];
        m = fmaxf(m, v[i]);
    }
    red[t] = m;
    __syncthreads();
    for (int s = 128; s > 0; s >>= 1) {
        if (t < s) red[t] = fmaxf(red[t], red[t + s]);
        __syncthreads();
    }
    float rowmax = red[0];
    __syncthreads();

    float sum = 0.f;
#pragma unroll
    for (int i = 0; i < 8; ++i) {
        v[i] = __expf(v[i] - rowmax);
        sum += v[i];
    }
    red[t] = sum;
    __syncthreads();
    for (int s = 128; s > 0; s >>= 1) {
        if (t < s) red[t] += red[t + s];
        __syncthreads();
    }
    float inv = 1.f / red[0];
#pragma unroll
    for (int i = 0; i < 8; ++i)
        g_sT[base + t + i * 256] = v[i] * inv;
}

// ---------------------------------------------------------------------------
// Kernel 4: out[b,c,j] = gamma * sum_l v[b,c,l] * sT[b,j,l].  TN GEMM,
// K = L = 2048, both operands K-contiguous; transpose-load into smem.
// ---------------------------------------------------------------------------
__global__ __launch_bounds__(256, 2)
void out_kernel(float* __restrict__ out, const float* __restrict__ gamma) {
    __shared__ float As[8][128];   // [l][c]
    __shared__ float Bs[8][128];   // [l][j]

    const int b  = blockIdx.z;
    const int c0 = blockIdx.y * 128;
    const int j0 = blockIdx.x * 128;
    const int t  = threadIdx.x;
    const int m0 = (t >> 4) * 8;
    const int n0 = (t & 15) * 8;

    const int x_row = t >> 1;          // which c (or j) row this thread loads
    const int x_r4  = (t & 1) * 4;     // which 4 l's

    const float* vbase  = &g_v[((size_t)b * C_ + c0 + x_row) * L_];
    const float* sbase  = &g_sT[((size_t)b * L_ + j0 + x_row) * L_];

    float acc[8][8];
#pragma unroll
    for (int i = 0; i < 8; ++i)
#pragma unroll
        for (int j = 0; j < 8; ++j) acc[i][j] = 0.f;

    for (int kb = 0; kb < L_; kb += 8) {
        float4 a4 = *reinterpret_cast<const float4*>(vbase + kb + x_r4);
        float4 b4 = *reinterpret_cast<const float4*>(sbase + kb + x_r4);
        As[x_r4 + 0][x_row] = a4.x;
        As[x_r4 + 1][x_row] = a4.y;
        As[x_r4 + 2][x_row] = a4.z;
        As[x_r4 + 3][x_row] = a4.w;
        Bs[x_r4 + 0][x_row] = b4.x;
        Bs[x_r4 + 1][x_row] = b4.y;
        Bs[x_r4 + 2][x_row] = b4.z;
        Bs[x_r4 + 3][x_row] = b4.w;
        __syncthreads();

#pragma unroll
        for (int r = 0; r < 8; ++r) {
            float4 a0 = *reinterpret_cast<const float4*>(&As[r][m0]);
            float4 a1 = *reinterpret_cast<const float4*>(&As[r][m0 + 4]);
            float4 b0 = *reinterpret_cast<const float4*>(&Bs[r][n0]);
            float4 b1 = *reinterpret_cast<const float4*>(&Bs[r][n0 + 4]);
            float av[8] = {a0.x, a0.y, a0.z, a0.w, a1.x, a1.y, a1.z, a1.w};
            float bv[8] = {b0.x, b0.y, b0.z, b0.w, b1.x, b1.y, b1.z, b1.w};
#pragma unroll
            for (int mi = 0; mi < 8; ++mi)
#pragma unroll
                for (int ni = 0; ni < 8; ++ni)
                    acc[mi][ni] += av[mi] * bv[ni];
        }
        __syncthreads();
    }

    const float g = __ldg(gamma);
#pragma unroll
    for (int mi = 0; mi < 8; ++mi) {
        size_t rowb = ((size_t)b * C_ + c0 + m0 + mi) * L_;
#pragma unroll
        for (int ni = 0; ni < 8; ++ni)
            out[rowb + j0 + n0 + ni] = g * acc[mi][ni];
    }
}

// ---------------------------------------------------------------------------
extern "C" void kernel_launch(void* const* d_in, const int* in_sizes, int n_in,
                              void* d_out, int out_size) {
    const float* x     = (const float*)d_in[0];
    const float* Wq    = (const float*)d_in[1];
    const float* Wk    = (const float*)d_in[2];
    const float* Wv    = (const float*)d_in[3];
    const float* gamma = (const float*)d_in[4];
    float* out = (float*)d_out;

    {
        dim3 grid(L_ / 128, COUT / 128, B_);   // 16 x 5 x 8
        conv_qkv_kernel<<<grid, 256>>>(x, Wq, Wk, Wv);
    }
    {
        dim3 grid(L_ / 128, L_ / 128, B_);     // 16 x 16 x 8
        scores_kernel<<<grid, 256>>>();
    }
    {
        softmax_kernel<<<B_ * L_, 256>>>();    // 16384 rows
    }
    {
        dim3 grid(L_ / 128, C_ / 128, B_);     // 16 x 4 x 8
        out_kernel<<<grid, 256>>>(out, gamma);
    }
}

// round 3
// speedup vs baseline: 2.0637x; 2.0637x over previous
#include <cuda_runtime.h>
#include <cstdint>
#include <cfloat>

#define B_  8
#define C_  512
#define L_  2048
#define CQ_ 64
#define KW  3
#define CK  (C_ * KW)   // 1536
#define LDS 20          // padded smem row stride (floats) -> conflict-free mma frag reads

// Scratch (allocation-free rule: __device__ globals)
__device__ float g_q[B_ * CQ_ * L_];            // 4 MB
__device__ float g_k[B_ * CQ_ * L_];            // 4 MB
__device__ float g_v[B_ * C_ * L_];             // 32 MB
__device__ float g_sT[(size_t)B_ * L_ * L_];    // 128 MB  (scores^T, softmaxed in place)

// ---------------------------------------------------------------------------
// tf32 mma helpers
// ---------------------------------------------------------------------------
__device__ __forceinline__ uint32_t f2tf(float x) {
    uint32_t r;
    asm("cvt.rna.tf32.f32 %0, %1;" : "=r"(r) : "f"(x));
    return r;
}

__device__ __forceinline__ void mma_tf32(float& d0, float& d1, float& d2, float& d3,
                                         uint32_t a0, uint32_t a1, uint32_t a2, uint32_t a3,
                                         uint32_t b0, uint32_t b1) {
    asm volatile(
        "mma.sync.aligned.m16n8k8.row.col.f32.tf32.tf32.f32 "
        "{%0,%1,%2,%3}, {%4,%5,%6,%7}, {%8,%9}, {%0,%1,%2,%3};"
        : "+f"(d0), "+f"(d1), "+f"(d2), "+f"(d3)
        : "r"(a0), "r"(a1), "r"(a2), "r"(a3), "r"(b0), "r"(b1));
}

// ---------------------------------------------------------------------------
// Kernel 1a: q/k conv (128 output channels) — FFMA, kept in full fp32 for the
// accuracy-critical score path.
// ---------------------------------------------------------------------------
__device__ __forceinline__ const float* wrow_qk(const float* __restrict__ Wq,
                                                const float* __restrict__ Wk,
                                                int o) {
    return (o < CQ_) ? Wq + (size_t)o * CK : Wk + (size_t)(o - CQ_) * CK;
}

__global__ __launch_bounds__(256, 2)
void conv_qk_kernel(const float* __restrict__ x,
                    const float* __restrict__ Wq,
                    const float* __restrict__ Wk) {
    __shared__ float As[8][128];   // [kchunk][o]
    __shared__ float Bs[8][128];   // [kchunk][l]

    const int b  = blockIdx.z;
    const int l0 = blockIdx.x * 128;
    const int t  = threadIdx.x;

    const int m0 = (t >> 4) * 8;
    const int n0 = (t & 15) * 8;

    const int a_oo = t >> 1;
    const int a_r4 = (t & 1) * 4;
    const float* wr = wrow_qk(Wq, Wk, a_oo);

    float acc[8][8];
#pragma unroll
    for (int i = 0; i < 8; ++i)
#pragma unroll
        for (int j = 0; j < 8; ++j) acc[i][j] = 0.f;

    for (int kb = 0; kb < CK; kb += 8) {
        float4 wv4 = *reinterpret_cast<const float4*>(wr + kb + a_r4);
        As[a_r4 + 0][a_oo] = wv4.x;
        As[a_r4 + 1][a_oo] = wv4.y;
        As[a_r4 + 2][a_oo] = wv4.z;
        As[a_r4 + 3][a_oo] = wv4.w;

#pragma unroll
        for (int i = t; i < 8 * 128; i += 256) {
            int r  = i >> 7;
            int ll = i & 127;
            int kidx = kb + r;
            int ci = kidx / 3;
            int kk = kidx - ci * 3;
            int lpos = l0 + ll + kk - 1;
            float xv = 0.f;
            if (lpos >= 0 && lpos < L_)
                xv = x[((size_t)b * C_ + ci) * L_ + lpos];
            Bs[r][ll] = xv;
        }
        __syncthreads();

#pragma unroll
        for (int r = 0; r < 8; ++r) {
            float4 a0 = *reinterpret_cast<const float4*>(&As[r][m0]);
            float4 a1 = *reinterpret_cast<const float4*>(&As[r][m0 + 4]);
            float4 b0 = *reinterpret_cast<const float4*>(&Bs[r][n0]);
            float4 b1 = *reinterpret_cast<const float4*>(&Bs[r][n0 + 4]);
            float av[8] = {a0.x, a0.y, a0.z, a0.w, a1.x, a1.y, a1.z, a1.w};
            float bv[8] = {b0.x, b0.y, b0.z, b0.w, b1.x, b1.y, b1.z, b1.w};
#pragma unroll
            for (int mi = 0; mi < 8; ++mi)
#pragma unroll
                for (int ni = 0; ni < 8; ++ni)
                    acc[mi][ni] += av[mi] * bv[ni];
        }
        __syncthreads();
    }

#pragma unroll
    for (int mi = 0; mi < 8; ++mi) {
        int o = m0 + mi;
        float* dst = (o < CQ_) ? &g_q[((size_t)b * CQ_ + o) * L_]
                               : &g_k[((size_t)b * CQ_ + (o - CQ_)) * L_];
#pragma unroll
        for (int ni = 0; ni < 8; ++ni)
            dst[l0 + n0 + ni] = acc[mi][ni];
    }
}

// ---------------------------------------------------------------------------
// Kernel 1b: v conv (512 channels) — tf32 mma implicit GEMM.
// M = out channel (128/CTA), N = l (128/CTA), K over (ci,kk) = 1536.
// ---------------------------------------------------------------------------
__global__ __launch_bounds__(256, 2)
void conv_v_mma_kernel(const float* __restrict__ x,
                       const float* __restrict__ Wv) {
    __shared__ uint32_t As[128 * LDS];   // [o][k] tf32
    __shared__ uint32_t Bs[128 * LDS];   // [l][k] tf32

    const int b  = blockIdx.z;
    const int o0 = blockIdx.y * 128;
    const int l0 = blockIdx.x * 128;
    const int t  = threadIdx.x;
    const int warp = t >> 5;
    const int lane = t & 31;
    const int wm = (warp >> 2) * 64;   // warp m offset (0/64)
    const int wn = (warp & 3) * 32;    // warp n offset
    const int group = lane >> 2;
    const int tid4  = lane & 3;

    float acc[4][4][4];
#pragma unroll
    for (int mi = 0; mi < 4; ++mi)
#pragma unroll
        for (int ni = 0; ni < 4; ++ni)
#pragma unroll
            for (int r = 0; r < 4; ++r) acc[mi][ni][r] = 0.f;

    for (int kb = 0; kb < CK; kb += 16) {
        // A: weights, 128 rows x 16 k, row-contiguous in gmem
#pragma unroll
        for (int i = 0; i < 2; ++i) {
            int idx = t + i * 256;          // 0..511 float4 slots
            int row = idx >> 2;
            int c4  = idx & 3;
            float4 w4 = *reinterpret_cast<const float4*>(
                Wv + (size_t)(o0 + row) * CK + kb + c4 * 4);
            uint32_t* dst = &As[row * LDS + c4 * 4];
            dst[0] = f2tf(w4.x); dst[1] = f2tf(w4.y);
            dst[2] = f2tf(w4.z); dst[3] = f2tf(w4.w);
        }
        // B: im2col(x), [l][k]
#pragma unroll
        for (int i = 0; i < 8; ++i) {
            int idx = t + i * 256;          // 0..2047
            int r  = idx >> 7;              // k row 0..15
            int ll = idx & 127;
            int kidx = kb + r;
            int ci = kidx / 3;
            int kk = kidx - ci * 3;
            int lpos = l0 + ll + kk - 1;
            float xv = 0.f;
            if (lpos >= 0 && lpos < L_)
                xv = x[((size_t)b * C_ + ci) * L_ + lpos];
            Bs[ll * LDS + r] = f2tf(xv);
        }
        __syncthreads();

#pragma unroll
        for (int ks = 0; ks < 2; ++ks) {
            const int ko = ks * 8;
            uint32_t af[4][4];
#pragma unroll
            for (int mi = 0; mi < 4; ++mi) {
                int r0 = wm + mi * 16 + group;
                af[mi][0] = As[r0 * LDS + ko + tid4];
                af[mi][1] = As[(r0 + 8) * LDS + ko + tid4];
                af[mi][2] = As[r0 * LDS + ko + tid4 + 4];
                af[mi][3] = As[(r0 + 8) * LDS + ko + tid4 + 4];
            }
            uint32_t bf[4][2];
#pragma unroll
            for (int ni = 0; ni < 4; ++ni) {
                int n0r = wn + ni * 8 + group;
                bf[ni][0] = Bs[n0r * LDS + ko + tid4];
                bf[ni][1] = Bs[n0r * LDS + ko + tid4 + 4];
            }
#pragma unroll
            for (int mi = 0; mi < 4; ++mi)
#pragma unroll
                for (int ni = 0; ni < 4; ++ni)
                    mma_tf32(acc[mi][ni][0], acc[mi][ni][1], acc[mi][ni][2], acc[mi][ni][3],
                             af[mi][0], af[mi][1], af[mi][2], af[mi][3],
                             bf[ni][0], bf[ni][1]);
        }
        __syncthreads();
    }

#pragma unroll
    for (int mi = 0; mi < 4; ++mi) {
#pragma unroll
        for (int ni = 0; ni < 4; ++ni) {
            int o  = o0 + wm + mi * 16 + group;
            int cl = l0 + wn + ni * 8 + tid4 * 2;
            float2 v01 = make_float2(acc[mi][ni][0], acc[mi][ni][1]);
            float2 v23 = make_float2(acc[mi][ni][2], acc[mi][ni][3]);
            *reinterpret_cast<float2*>(&g_v[((size_t)b * C_ + o) * L_ + cl])       = v01;
            *reinterpret_cast<float2*>(&g_v[((size_t)b * C_ + o + 8) * L_ + cl])   = v23;
        }
    }
}

// ---------------------------------------------------------------------------
// Kernel 2: scores^T (fp32 FFMA — accuracy critical).
// sT[b, j, i] = sum_c k[b,c,j] * q[b,c,i].  K = 64.
// ---------------------------------------------------------------------------
__global__ __launch_bounds__(256, 2)
void scores_kernel() {
    __shared__ float As[8][128];
    __shared__ float Bs[8][128];

    const int b  = blockIdx.z;
    const int j0 = blockIdx.y * 128;
    const int i0 = blockIdx.x * 128;
    const int t  = threadIdx.x;
    const int m0 = (t >> 4) * 8;
    const int n0 = (t & 15) * 8;

    float acc[8][8];
#pragma unroll
    for (int i = 0; i < 8; ++i)
#pragma unroll
        for (int j = 0; j < 8; ++j) acc[i][j] = 0.f;

    for (int kb = 0; kb < CQ_; kb += 8) {
#pragma unroll
        for (int i = t; i < 8 * 128; i += 256) {
            int r  = i >> 7;
            int cc = i & 127;
            size_t rowb = ((size_t)b * CQ_ + kb + r) * L_;
            As[r][cc] = g_k[rowb + j0 + cc];
            Bs[r][cc] = g_q[rowb + i0 + cc];
        }
        __syncthreads();

#pragma unroll
        for (int r = 0; r < 8; ++r) {
            float4 a0 = *reinterpret_cast<const float4*>(&As[r][m0]);
            float4 a1 = *reinterpret_cast<const float4*>(&As[r][m0 + 4]);
            float4 b0 = *reinterpret_cast<const float4*>(&Bs[r][n0]);
            float4 b1 = *reinterpret_cast<const float4*>(&Bs[r][n0 + 4]);
            float av[8] = {a0.x, a0.y, a0.z, a0.w, a1.x, a1.y, a1.z, a1.w};
            float bv[8] = {b0.x, b0.y, b0.z, b0.w, b1.x, b1.y, b1.z, b1.w};
#pragma unroll
            for (int mi = 0; mi < 8; ++mi)
#pragma unroll
                for (int ni = 0; ni < 8; ++ni)
                    acc[mi][ni] += av[mi] * bv[ni];
        }
        __syncthreads();
    }

#pragma unroll
    for (int mi = 0; mi < 8; ++mi) {
        size_t rowb = ((size_t)b * L_ + j0 + m0 + mi) * L_;
#pragma unroll
        for (int ni = 0; ni < 8; ++ni)
            g_sT[rowb + i0 + n0 + ni] = acc[mi][ni];
    }
}

// ---------------------------------------------------------------------------
// Kernel 3: in-place row softmax over sT rows.
// ---------------------------------------------------------------------------
__global__ __launch_bounds__(256)
void softmax_kernel() {
    __shared__ float red[256];
    const int row = blockIdx.x;
    const int t   = threadIdx.x;
    size_t base = (size_t)row * L_;

    float v[8];
    float m = -FLT_MAX;
#pragma unroll
    for (int i = 0; i < 8; ++i) {
        v[i] = g_sT[base + t + i * 256];
        m = fmaxf(m, v[i]);
    }
    red[t] = m;
    __syncthreads();
    for (int s = 128; s > 0; s >>= 1) {
        if (t < s) red[t] = fmaxf(red[t], red[t + s]);
        __syncthreads();
    }
    float rowmax = red[0];
    __syncthreads();

    float sum = 0.f;
#pragma unroll
    for (int i = 0; i < 8; ++i) {
        v[i] = __expf(v[i] - rowmax);
        sum += v[i];
    }
    red[t] = sum;
    __syncthreads();
    for (int s = 128; s > 0; s >>= 1) {
        if (t < s) red[t] += red[t + s];
        __syncthreads();
    }
    float inv = 1.f / red[0];
#pragma unroll
    for (int i = 0; i < 8; ++i)
        g_sT[base + t + i * 256] = v[i] * inv;
}

// ---------------------------------------------------------------------------
// Kernel 4: out[b,c,j] = gamma * sum_l v[b,c,l] * sT[b,j,l] — tf32 mma TN GEMM.
// ---------------------------------------------------------------------------
__global__ __launch_bounds__(256, 2)
void out_mma_kernel(float* __restrict__ out, const float* __restrict__ gamma) {
    __shared__ uint32_t As[128 * LDS];   // [c][l] tf32
    __shared__ uint32_t Bs[128 * LDS];   // [j][l] tf32

    const int b  = blockIdx.z;
    const int c0 = blockIdx.y * 128;
    const int j0 = blockIdx.x * 128;
    const int t  = threadIdx.x;
    const int warp = t >> 5;
    const int lane = t & 31;
    const int wm = (warp >> 2) * 64;
    const int wn = (warp & 3) * 32;
    const int group = lane >> 2;
    const int tid4  = lane & 3;

    const float* abase = &g_v[((size_t)b * C_ + c0) * L_];
    const float* bbase = &g_sT[((size_t)b * L_ + j0) * L_];

    float acc[4][4][4];
#pragma unroll
    for (int mi = 0; mi < 4; ++mi)
#pragma unroll
        for (int ni = 0; ni < 4; ++ni)
#pragma unroll
            for (int r = 0; r < 4; ++r) acc[mi][ni][r] = 0.f;

    for (int kb = 0; kb < L_; kb += 16) {
#pragma unroll
        for (int i = 0; i < 2; ++i) {
            int idx = t + i * 256;
            int row = idx >> 2;
            int c4  = idx & 3;
            float4 a4 = *reinterpret_cast<const float4*>(abase + (size_t)row * L_ + kb + c4 * 4);
            float4 b4 = *reinterpret_cast<const float4*>(bbase + (size_t)row * L_ + kb + c4 * 4);
            uint32_t* da = &As[row * LDS + c4 * 4];
            da[0] = f2tf(a4.x); da[1] = f2tf(a4.y); da[2] = f2tf(a4.z); da[3] = f2tf(a4.w);
            uint32_t* db = &Bs[row * LDS + c4 * 4];
            db[0] = f2tf(b4.x); db[1] = f2tf(b4.y); db[2] = f2tf(b4.z); db[3] = f2tf(b4.w);
        }
        __syncthreads();

#pragma unroll
        for (int ks = 0; ks < 2; ++ks) {
            const int ko = ks * 8;
            uint32_t af[4][4];
#pragma unroll
            for (int mi = 0; mi < 4; ++mi) {
                int r0 = wm + mi * 16 + group;
                af[mi][0] = As[r0 * LDS + ko + tid4];
                af[mi][1] = As[(r0 + 8) * LDS + ko + tid4];
                af[mi][2] = As[r0 * LDS + ko + tid4 + 4];
                af[mi][3] = As[(r0 + 8) * LDS + ko + tid4 + 4];
            }
            uint32_t bf[4][2];
#pragma unroll
            for (int ni = 0; ni < 4; ++ni) {
                int n0r = wn + ni * 8 + group;
                bf[ni][0] = Bs[n0r * LDS + ko + tid4];
                bf[ni][1] = Bs[n0r * LDS + ko + tid4 + 4];
            }
#pragma unroll
            for (int mi = 0; mi < 4; ++mi)
#pragma unroll
                for (int ni = 0; ni < 4; ++ni)
                    mma_tf32(acc[mi][ni][0], acc[mi][ni][1], acc[mi][ni][2], acc[mi][ni][3],
                             af[mi][0], af[mi][1], af[mi][2], af[mi][3],
                             bf[ni][0], bf[ni][1]);
        }
        __syncthreads();
    }

    const float g = __ldg(gamma);
#pragma unroll
    for (int mi = 0; mi < 4; ++mi) {
#pragma unroll
        for (int ni = 0; ni < 4; ++ni) {
            int c  = c0 + wm + mi * 16 + group;
            int cl = j0 + wn + ni * 8 + tid4 * 2;
            float2 v01 = make_float2(g * acc[mi][ni][0], g * acc[mi][ni][1]);
            float2 v23 = make_float2(g * acc[mi][ni][2], g * acc[mi][ni][3]);
            *reinterpret_cast<float2*>(&out[((size_t)b * C_ + c) * L_ + cl])     = v01;
            *reinterpret_cast<float2*>(&out[((size_t)b * C_ + c + 8) * L_ + cl]) = v23;
        }
    }
}

// ---------------------------------------------------------------------------
extern "C" void kernel_launch(void* const* d_in, const int* in_sizes, int n_in,
                              void* d_out, int out_size) {
    const float* x     = (const float*)d_in[0];
    const float* Wq    = (const float*)d_in[1];
    const float* Wk    = (const float*)d_in[2];
    const float* Wv    = (const float*)d_in[3];
    const float* gamma = (const float*)d_in[4];
    float* out = (float*)d_out;

    {
        dim3 grid(L_ / 128, 1, B_);            // q,k channels (128)
        conv_qk_kernel<<<grid, 256>>>(x, Wq, Wk);
    }
    {
        dim3 grid(L_ / 128, C_ / 128, B_);     // v channels (512)
        conv_v_mma_kernel<<<grid, 256>>>(x, Wv);
    }
    {
        dim3 grid(L_ / 128, L_ / 128, B_);
        scores_kernel<<<grid, 256>>>();
    }
    {
        softmax_kernel<<<B_ * L_, 256>>>();
    }
    {
        dim3 grid(L_ / 128, C_ / 128, B_);
        out_mma_kernel<<<grid, 256>>>(out, gamma);
    }
}